// round 1
// baseline (speedup 1.0000x reference)
#include <cuda_runtime.h>
#include <math.h>

#define DDIM 128
#define NMAX 50000
#define EMAX 800000

// Scratch (alloc-free rule: __device__ globals)
__device__ float g_support[(size_t)NMAX * DDIM];
__device__ float g_agg[(size_t)NMAX * DDIM];

// ---------------------------------------------------------------------------
// Zero the aggregation buffer (float4 stores)
// ---------------------------------------------------------------------------
__global__ void zero_agg_kernel(int total4) {
    int i = blockIdx.x * blockDim.x + threadIdx.x;
    if (i < total4) ((float4*)g_agg)[i] = make_float4(0.f, 0.f, 0.f, 0.f);
}

// ---------------------------------------------------------------------------
// GEMM: 64-row x 128-col tile per block, 256 threads, 4x8 register tile.
// MODE 0: out = X @ W + b                      (support = x @ W_gc + b_gc)
// MODE 1: out = rownorm(relu(X) @ W^T + b)     (final output, fused epilogue)
// ---------------------------------------------------------------------------
template <int MODE>
__global__ void gemm_kernel(const float* __restrict__ X,
                            const float* __restrict__ W,
                            const float* __restrict__ bias,
                            float* __restrict__ out, int n) {
    __shared__ float xs[64][33];    // +1 pad
    __shared__ float ws[32][129];   // +1 pad (odd stride -> conflict-free transpose)

    const int tid = threadIdx.x;           // 256 threads
    const int tx = tid & 15;               // 16 threads over columns (stride 16)
    const int ty = tid >> 4;               // 16 thread groups over rows (4 rows each)
    const int r0 = blockIdx.x * 64;

    float acc[4][8];
#pragma unroll
    for (int i = 0; i < 4; i++)
#pragma unroll
        for (int c = 0; c < 8; c++) acc[i][c] = 0.f;

    for (int k0 = 0; k0 < DDIM; k0 += 32) {
        // --- load X tile [64 x 32], coalesced; ReLU fused for MODE 1 ---
        {
            int kk = tid & 31, r = tid >> 5;
#pragma unroll
            for (int rr = 0; rr < 8; rr++) {
                int row = r0 + r + rr * 8;
                float v = 0.f;
                if (row < n) {
                    v = X[(size_t)row * DDIM + k0 + kk];
                    if (MODE == 1) v = fmaxf(v, 0.f);
                }
                xs[r + rr * 8][kk] = v;
            }
        }
        // --- load W tile [32 x 128] into ws[k][j] ---
        if (MODE == 0) {
            // W row-major [k][j]: coalesced copy
            int j = tid & 127, kk = tid >> 7;
#pragma unroll
            for (int t = 0; t < 16; t++) ws[kk + 2 * t][j] = W[(size_t)(k0 + kk + 2 * t) * DDIM + j];
        } else {
            // need W^T: ws[k][j] = W[j][k]; read coalesced along k, padded smem write
            int kk = tid & 31, j0 = tid >> 5;
#pragma unroll
            for (int t = 0; t < 16; t++) {
                int j = j0 + 8 * t;
                ws[kk][j] = W[(size_t)j * DDIM + k0 + kk];
            }
        }
        __syncthreads();

        // --- 4x8 register-tile FMA over 32 k-steps ---
#pragma unroll
        for (int kk = 0; kk < 32; kk++) {
            float a[4], b[8];
#pragma unroll
            for (int i = 0; i < 4; i++) a[i] = xs[ty * 4 + i][kk];
#pragma unroll
            for (int c = 0; c < 8; c++) b[c] = ws[kk][tx + 16 * c];
#pragma unroll
            for (int i = 0; i < 4; i++)
#pragma unroll
                for (int c = 0; c < 8; c++) acc[i][c] = fmaf(a[i], b[c], acc[i][c]);
        }
        __syncthreads();
    }

    // --- epilogue ---
    float bv[8];
#pragma unroll
    for (int c = 0; c < 8; c++) bv[c] = bias[tx + 16 * c];

    if (MODE == 0) {
#pragma unroll
        for (int i = 0; i < 4; i++) {
            int row = r0 + ty * 4 + i;
            if (row < n) {
#pragma unroll
                for (int c = 0; c < 8; c++)
                    out[(size_t)row * DDIM + tx + 16 * c] = acc[i][c] + bv[c];
            }
        }
    } else {
        // fused L2 row-normalization: reduce sum-of-squares across the 16
        // tx-threads that share each row (half-warp shfl, width 16)
#pragma unroll
        for (int i = 0; i < 4; i++) {
            int row = r0 + ty * 4 + i;
            float v[8];
            float ss = 0.f;
#pragma unroll
            for (int c = 0; c < 8; c++) {
                v[c] = acc[i][c] + bv[c];
                ss = fmaf(v[c], v[c], ss);
            }
#pragma unroll
            for (int off = 8; off; off >>= 1)
                ss += __shfl_xor_sync(0xffffffffu, ss, off, 16);
            float nrm = sqrtf(ss);
            if (row < n) {
#pragma unroll
                for (int c = 0; c < 8; c++)
                    out[(size_t)row * DDIM + tx + 16 * c] = v[c] / nrm;
            }
        }
    }
}

// ---------------------------------------------------------------------------
// Edge scatter: one warp per edge. Gather support[src] (float4/lane), scale by
// vals[e], vector reduce-add into agg[dst]. Both buffers are L2-resident.
// ---------------------------------------------------------------------------
__global__ void scatter_kernel(const int* __restrict__ src,
                               const int* __restrict__ dst,
                               const float* __restrict__ vals, int e) {
    int g = blockIdx.x * blockDim.x + threadIdx.x;
    int edge = g >> 5;
    int lane = g & 31;
    if (edge >= e) return;
    int s = __ldg(src + edge);
    int d = __ldg(dst + edge);
    float v = __ldg(vals + edge);
    float4 m = ((const float4*)(g_support + (size_t)s * DDIM))[lane];
    m.x *= v; m.y *= v; m.z *= v; m.w *= v;
    float* a = g_agg + (size_t)d * DDIM + lane * 4;
    asm volatile("red.global.add.v4.f32 [%0], {%1, %2, %3, %4};"
                 :: "l"(a), "f"(m.x), "f"(m.y), "f"(m.z), "f"(m.w)
                 : "memory");
}

// ---------------------------------------------------------------------------
extern "C" void kernel_launch(void* const* d_in, const int* in_sizes, int n_in,
                              void* d_out, int out_size) {
    const float* x    = (const float*)d_in[0];
    const float* vals = (const float*)d_in[1];
    const float* W_gc = (const float*)d_in[2];
    const float* b_gc = (const float*)d_in[3];
    const float* W2   = (const float*)d_in[4];
    const float* b2   = (const float*)d_in[5];
    const int*   src  = (const int*)d_in[6];
    const int*   dst  = (const int*)d_in[7];

    const int n = in_sizes[0] / DDIM;
    const int e = in_sizes[1];

    float *support, *agg;
    cudaGetSymbolAddress((void**)&support, g_support);
    cudaGetSymbolAddress((void**)&agg, g_agg);

    // 1) zero agg  2) support = x @ W_gc + b_gc
    int total4 = n * (DDIM / 4);
    zero_agg_kernel<<<(total4 + 255) / 256, 256>>>(total4);

    int gblocks = (n + 63) / 64;
    gemm_kernel<0><<<gblocks, 256>>>(x, W_gc, b_gc, support, n);

    // 3) agg[dst] += support[src] * vals  (one warp per edge)
    long long sthreads = (long long)e * 32;
    scatter_kernel<<<(int)((sthreads + 255) / 256), 256>>>(src, dst, vals, e);

    // 4) out = rownorm(relu(agg) @ W2^T + b2)
    gemm_kernel<1><<<gblocks, 256>>>(agg, W2, b2, (float*)d_out, n);
}